// round 11
// baseline (speedup 1.0000x reference)
#include <cuda_runtime.h>
#include <cuda_fp16.h>
#include <cstdint>

#define B_  4
#define H_  16
#define T_  2048
#define DK_ 64
#define DM_ 1024
#define M_  (B_*T_)     // 8192

// ---------------- scratch (device globals; no allocations allowed) ----------
__device__ __half g_xh[M_*DM_];
__device__ __half g_wh[4*DM_*DM_];   // Wq | Wk | Wv | Wo (contiguous)
__device__ __half g_qh[M_*DM_];      // [b,h,t,d]
__device__ __half g_kh[M_*DM_];      // [b,h,t,d]
__device__ __half g_vh[M_*DM_];      // [b,h,d,t]  (transposed!)
__device__ __half g_ah[M_*DM_];      // [b,t, h*64+d]

// ---------------- portable PTX helpers (family-safe) -------------------------
__device__ __forceinline__ uint32_t smem_u32(const void* p) {
    uint32_t a;
    asm("{ .reg .u64 t; cvta.to.shared.u64 t, %1; cvt.u32.u64 %0, t; }" : "=r"(a) : "l"(p));
    return a;
}
__device__ __forceinline__ void cp_async16(uint32_t saddr, const void* gaddr) {
    asm volatile("cp.async.cg.shared.global [%0], [%1], 16;" :: "r"(saddr), "l"(gaddr));
}
#define CP_COMMIT() asm volatile("cp.async.commit_group;" ::: "memory")
#define CP_WAIT(n)  asm volatile("cp.async.wait_group %0;" :: "n"(n) : "memory")

__device__ __forceinline__ void ldsm_x4(uint32_t addr, uint32_t& r0, uint32_t& r1,
                                        uint32_t& r2, uint32_t& r3) {
    asm volatile("ldmatrix.sync.aligned.m8n8.x4.shared.b16 {%0,%1,%2,%3}, [%4];"
                 : "=r"(r0), "=r"(r1), "=r"(r2), "=r"(r3) : "r"(addr));
}
__device__ __forceinline__ void mma_f16(float* c, const uint32_t* a, const uint32_t* b) {
    asm volatile(
        "mma.sync.aligned.m16n8k16.row.col.f32.f16.f16.f32 "
        "{%0,%1,%2,%3}, {%4,%5,%6,%7}, {%8,%9}, {%0,%1,%2,%3};"
        : "+f"(c[0]), "+f"(c[1]), "+f"(c[2]), "+f"(c[3])
        : "r"(a[0]), "r"(a[1]), "r"(a[2]), "r"(a[3]), "r"(b[0]), "r"(b[1]));
}
__device__ __forceinline__ uint32_t pack_half2(float a, float b) {
    __half2 h = __floats2half2_rn(a, b);
    return *(uint32_t*)&h;
}

// ---------------- fp32 -> fp16 converts ---------------------------------------
__global__ __launch_bounds__(256) void tohalf_kernel(
    const float* __restrict__ x, __half* __restrict__ y, int n4)
{
    int i = blockIdx.x * blockDim.x + threadIdx.x;
    if (i >= n4) return;
    float4 v = ((const float4*)x)[i];
    uint2 o;
    o.x = pack_half2(v.x, v.y);
    o.y = pack_half2(v.z, v.w);
    ((uint2*)y)[i] = o;
}

// all 4 weight matrices in one launch (grid.y selects source)
__global__ __launch_bounds__(256) void tohalf_w_kernel(
    const float* __restrict__ s0, const float* __restrict__ s1,
    const float* __restrict__ s2, const float* __restrict__ s3,
    __half* __restrict__ y, int n4)
{
    int i = blockIdx.x * blockDim.x + threadIdx.x;
    if (i >= n4) return;
    const float* src = (blockIdx.y == 0) ? s0 : (blockIdx.y == 1) ? s1
                     : (blockIdx.y == 2) ? s2 : s3;
    float4 v = ((const float4*)src)[i];
    uint2 o;
    o.x = pack_half2(v.x, v.y);
    o.y = pack_half2(v.z, v.w);
    ((uint2*)(y + (size_t)blockIdx.y * DM_ * DM_))[i] = o;
}

// ---------------- mma.sync fp16 GEMM -----------------------------------------
// CTA 128(m) x 128(n), BK=64, 3-stage cp.async, 256 thr = 8 warps 4(m)x2(n),
// warp tile 32x64. mode 0: fused QKV epilogue (N=3072, n>>10 selects Q/K/V);
// mode 1: fp32 row-major out (+bias).
#define GPH 72                              // smem pitch (fp16): 144B rows
#define GT_BYTES (128 * GPH * 2)            // 18432 B per 128x64 tile
#define G_STAGE (2 * GT_BYTES)              // 36864 B (A, B)
#define G_SMEM (3 * G_STAGE)                // 110592 B -> 2 CTAs/SM

__device__ __forceinline__ void gemm_issue_stage(uint32_t base,
    const __half* __restrict__ Ah, const __half* __restrict__ Wh,
    int m0, int n0, int k0, int tid)
{
    // each tile: 128 rows x 128B (8 x 16B chunks) = 1024 chunks / 256 thr = 4 iters
    #pragma unroll
    for (int it = 0; it < 4; it++) {
        int idx = it * 256 + tid;
        int r = idx >> 3, c = idx & 7;
        const uint32_t so = r * (GPH * 2) + c * 16;
        cp_async16(base + so,            Ah + (size_t)(m0 + r) * 1024 + k0 + c * 8);
        cp_async16(base + GT_BYTES + so, Wh + (size_t)(n0 + r) * 1024 + k0 + c * 8);
    }
}

__global__ __launch_bounds__(256, 2) void gemm_tc_kernel(
    const __half* __restrict__ Ah, const __half* __restrict__ Wh,
    const float* __restrict__ bias0, const float* __restrict__ bias1,
    const float* __restrict__ bias2,
    __half* __restrict__ Qh, __half* __restrict__ Kh, __half* __restrict__ Vh,
    float* __restrict__ Cf, int mode)
{
    extern __shared__ char smem[];
    const uint32_t sb = smem_u32(smem);
    const int tid = threadIdx.x;
    const int wid = tid >> 5, lane = tid & 31;
    const int m0 = blockIdx.y * 128, n0 = blockIdx.x * 128;
    const int wm = (wid & 3) * 32;        // warp m-offset
    const int wn = (wid >> 2) * 64;       // warp n-offset
    const int rl = lane & 7, q = lane >> 3;

    float acc[2][8][4];
    #pragma unroll
    for (int mt = 0; mt < 2; mt++)
        #pragma unroll
        for (int nt = 0; nt < 8; nt++)
            #pragma unroll
            for (int e = 0; e < 4; e++) acc[mt][nt][e] = 0.f;

    // prologue: stages 0,1 in flight
    #pragma unroll
    for (int p = 0; p < 2; p++) {
        gemm_issue_stage(sb + p * G_STAGE, Ah, Wh, m0, n0, p * 64, tid);
        CP_COMMIT();
    }

    const uint32_t a_row = rl + (q & 1) * 8;
    const uint32_t a_cofs = (q >> 1) * 8;
    const uint32_t b_row = rl + (q >> 1) * 8;
    const uint32_t b_cofs = (q & 1) * 8;

    uint32_t stage = 0;
    for (int s = 0; s < 16; s++) {
        if (s < 15) CP_WAIT(1); else CP_WAIT(0);
        __syncthreads();

        const uint32_t st = sb + stage * G_STAGE;

        #pragma unroll
        for (int kk = 0; kk < 4; kk++) {
            uint32_t af[2][4];
            #pragma unroll
            for (int mt = 0; mt < 2; mt++) {
                uint32_t ro = (wm + mt * 16 + a_row) * (GPH * 2) + (kk * 16 + a_cofs) * 2;
                ldsm_x4(st + ro, af[mt][0], af[mt][1], af[mt][2], af[mt][3]);
            }
            uint32_t bf[8][2];
            #pragma unroll
            for (int np = 0; np < 4; np++) {
                uint32_t ro = (wn + np * 16 + b_row) * (GPH * 2) + (kk * 16 + b_cofs) * 2;
                ldsm_x4(st + GT_BYTES + ro,
                        bf[np*2][0], bf[np*2][1], bf[np*2+1][0], bf[np*2+1][1]);
            }
            #pragma unroll
            for (int mt = 0; mt < 2; mt++)
                #pragma unroll
                for (int nt = 0; nt < 8; nt++)
                    mma_f16(acc[mt][nt], af[mt], bf[nt]);
        }

        if (s + 2 < 16) {
            uint32_t ns = (stage + 2 >= 3) ? (stage + 2 - 3) : (stage + 2);
            gemm_issue_stage(sb + ns * G_STAGE, Ah, Wh, m0, n0, (s + 2) * 64, tid);
            CP_COMMIT();
        }
        stage = (stage + 1 >= 3) ? 0 : (stage + 1);
    }

    // ---- epilogue
    const int g = lane >> 2, tq = lane & 3;
    const int which = (n0 >> 10);   // CTA-uniform (tile never crosses 1024)
    const float* bsel = (which == 0) ? bias0 : (which == 1) ? bias1 : bias2;

    #pragma unroll
    for (int mt = 0; mt < 2; mt++) {
        #pragma unroll
        for (int half = 0; half < 2; half++) {
            int m = m0 + wm + mt * 16 + g + half * 8;
            int b = m >> 11, t = m & 2047;
            #pragma unroll
            for (int nt = 0; nt < 8; nt++) {
                int n = n0 + wn + nt * 8 + 2 * tq;
                if (mode == 1) {
                    float2 v;
                    v.x = acc[mt][nt][half * 2 + 0] + __ldg(bias0 + n);
                    v.y = acc[mt][nt][half * 2 + 1] + __ldg(bias0 + n + 1);
                    *(float2*)(Cf + (size_t)m * 1024 + n) = v;
                } else {
                    int nn = n & 1023;
                    float vx = acc[mt][nt][half * 2 + 0] + __ldg(bsel + nn);
                    float vy = acc[mt][nt][half * 2 + 1] + __ldg(bsel + nn + 1);
                    int h = nn >> 6, d = nn & 63;
                    if (which == 2) {
                        // V transposed: [b,h,d,t]
                        size_t off = (((size_t)(b * 16 + h)) * 64 + d) * 2048 + t;
                        Vh[off]        = __float2half_rn(vx);
                        Vh[off + 2048] = __float2half_rn(vy);
                    } else {
                        size_t off = (((size_t)(b * 16 + h)) * 2048 + t) * 64 + d;
                        uint32_t pv = pack_half2(vx, vy);
                        if (which == 0) *(uint32_t*)(Qh + off) = pv;
                        else            *(uint32_t*)(Kh + off) = pv;
                    }
                }
            }
        }
    }
}

// ---------------- tensor-core flash attention (fp16, causal) -----------------
// grid (T/128, B*H), 256 thr = 8 warps; warp w owns Q rows w*16..w*16+15 of a
// 128-row Q tile. kv tiles of 64; K/V loads amortized over 2x rows vs 64-tile.
#define AP 72                              // smem pitch in fp16 (144B rows)
#define ATILE (64 * AP * 2)                // 9216 B per 64x64 tile
#define AQ_BYTES (128 * AP * 2)            // 18432 B (128-row Q tile)
#define AST_OFF AQ_BYTES
#define ASTAGE (2 * ATILE)                 // K, V
#define ATTN_SMEM (AQ_BYTES + 2 * ASTAGE)  // 55296 B

__device__ __forceinline__ void attn_load_tile64(uint32_t sbase,
    const __half* __restrict__ gsrc, int rowstride, int tid)
{
    // 64 rows x 8 chunks = 512 chunks / 256 thr = 2 iters
    #pragma unroll
    for (int it = 0; it < 2; it++) {
        int idx = it * 256 + tid;
        int r = idx >> 3, c = idx & 7;
        cp_async16(sbase + r * (AP * 2) + c * 16,
                   gsrc + (size_t)r * rowstride + c * 8);
    }
}

__global__ __launch_bounds__(256, 2) void attn_tc_kernel(
    const __half* __restrict__ Qh, const __half* __restrict__ Kh,
    const __half* __restrict__ VTh, __half* __restrict__ Ah)
{
    extern __shared__ char smem[];
    const uint32_t sb = smem_u32(smem);
    const int tid = threadIdx.x;
    const int w = tid >> 5, lane = tid & 31;
    const int qi = blockIdx.x, bh = blockIdx.y;
    const size_t baseTD = (size_t)bh * T_ * 64;
    const int rl = lane & 7, q = lane >> 3;
    const int g = lane >> 2, tq = lane & 3;
    const int nkv = 2 * qi + 2;            // kv tiles 0..2qi+1

    // Q tile: 128 rows x 8 chunks = 1024 chunks / 256 thr = 4 iters
    {
        const __half* qsrc = Qh + baseTD + (size_t)qi * 128 * 64;
        #pragma unroll
        for (int it = 0; it < 4; it++) {
            int idx = it * 256 + tid;
            int r = idx >> 3, c = idx & 7;
            cp_async16(sb + r * (AP * 2) + c * 16, qsrc + (size_t)r * 64 + c * 8);
        }
        CP_COMMIT();
    }
    {
        uint32_t st0 = sb + AST_OFF;
        attn_load_tile64(st0,         Kh + baseTD, 64, tid);
        attn_load_tile64(st0 + ATILE, VTh + baseTD, 2048, tid);
        CP_COMMIT();
    }

    CP_WAIT(1);
    __syncthreads();

    const uint32_t a_row = rl + (q & 1) * 8, a_cofs = (q >> 1) * 8;
    const uint32_t b_row = rl + (q >> 1) * 8, b_cofs = (q & 1) * 8;
    uint32_t qf[4][4];
    #pragma unroll
    for (int kk = 0; kk < 4; kk++) {
        uint32_t ro = (w * 16 + a_row) * (AP * 2) + (kk * 16 + a_cofs) * 2;
        ldsm_x4(sb + ro, qf[kk][0], qf[kk][1], qf[kk][2], qf[kk][3]);
    }

    float oacc[8][4];
    #pragma unroll
    for (int nt = 0; nt < 8; nt++)
        #pragma unroll
        for (int e = 0; e < 4; e++) oacc[nt][e] = 0.f;
    float m_r[2] = {-1e30f, -1e30f}, l_r[2] = {0.f, 0.f};

    for (int kt = 0; kt < nkv; kt++) {
        const uint32_t st = sb + AST_OFF + (kt & 1) * ASTAGE;
        if (kt + 1 < nkv) {
            uint32_t ns = sb + AST_OFF + ((kt + 1) & 1) * ASTAGE;
            attn_load_tile64(ns,         Kh + baseTD + (size_t)(kt + 1) * 64 * 64, 64, tid);
            attn_load_tile64(ns + ATILE, VTh + baseTD + (size_t)(kt + 1) * 64, 2048, tid);
            CP_COMMIT();
            CP_WAIT(1);
        } else {
            CP_WAIT(0);
        }
        __syncthreads();

        // ---- S = Q K^T
        float sacc[8][4];
        #pragma unroll
        for (int nt = 0; nt < 8; nt++)
            #pragma unroll
            for (int e = 0; e < 4; e++) sacc[nt][e] = 0.f;

        #pragma unroll
        for (int kk = 0; kk < 4; kk++) {
            uint32_t kf[8][2];
            #pragma unroll
            for (int np = 0; np < 4; np++) {
                uint32_t ro = (np * 16 + b_row) * (AP * 2) + (kk * 16 + b_cofs) * 2;
                ldsm_x4(st + ro,
                        kf[np*2][0], kf[np*2][1], kf[np*2+1][0], kf[np*2+1][1]);
            }
            #pragma unroll
            for (int nt = 0; nt < 8; nt++)
                mma_f16(sacc[nt], qf[kk], kf[nt]);
        }

        // ---- scale + causal mask (only last two tiles can touch diagonal)
        const bool diag = (kt >= 2 * qi);
        #pragma unroll
        for (int nt = 0; nt < 8; nt++) {
            #pragma unroll
            for (int e = 0; e < 4; e++) {
                float s = sacc[nt][e] * 0.125f;
                if (diag) {
                    int grow = qi * 128 + w * 16 + g + (e >> 1) * 8;
                    int gcol = kt * 64 + nt * 8 + 2 * tq + (e & 1);
                    if (gcol > grow) s = -1e30f;
                }
                sacc[nt][e] = s;
            }
        }

        // ---- online softmax (per thread: rows g, g+8)
        #pragma unroll
        for (int r = 0; r < 2; r++) {
            float mloc = -1e30f;
            #pragma unroll
            for (int nt = 0; nt < 8; nt++)
                mloc = fmaxf(mloc, fmaxf(sacc[nt][r*2], sacc[nt][r*2+1]));
            mloc = fmaxf(mloc, __shfl_xor_sync(0xffffffffu, mloc, 1));
            mloc = fmaxf(mloc, __shfl_xor_sync(0xffffffffu, mloc, 2));
            float mnew = fmaxf(m_r[r], mloc);
            float rs = 0.f;
            #pragma unroll
            for (int nt = 0; nt < 8; nt++) {
                float p0 = __expf(sacc[nt][r*2]   - mnew);
                float p1 = __expf(sacc[nt][r*2+1] - mnew);
                sacc[nt][r*2] = p0; sacc[nt][r*2+1] = p1;
                rs += p0 + p1;
            }
            rs += __shfl_xor_sync(0xffffffffu, rs, 1);
            rs += __shfl_xor_sync(0xffffffffu, rs, 2);
            float corr = __expf(m_r[r] - mnew);
            l_r[r] = l_r[r] * corr + rs;
            m_r[r] = mnew;
            #pragma unroll
            for (int nt = 0; nt < 8; nt++) {
                oacc[nt][r*2]   *= corr;
                oacc[nt][r*2+1] *= corr;
            }
        }

        // ---- O += P V
        #pragma unroll
        for (int j = 0; j < 4; j++) {
            uint32_t pf[4];
            pf[0] = pack_half2(sacc[2*j][0],   sacc[2*j][1]);
            pf[1] = pack_half2(sacc[2*j][2],   sacc[2*j][3]);
            pf[2] = pack_half2(sacc[2*j+1][0], sacc[2*j+1][1]);
            pf[3] = pack_half2(sacc[2*j+1][2], sacc[2*j+1][3]);

            uint32_t vf[8][2];
            #pragma unroll
            for (int np = 0; np < 4; np++) {
                uint32_t ro = (np * 16 + b_row) * (AP * 2) + (j * 16 + b_cofs) * 2;
                ldsm_x4(st + ATILE + ro,
                        vf[np*2][0], vf[np*2][1], vf[np*2+1][0], vf[np*2+1][1]);
            }
            #pragma unroll
            for (int nt = 0; nt < 8; nt++)
                mma_f16(oacc[nt], pf, vf[nt]);
        }
        __syncthreads();
    }

    // ---- epilogue: normalize, write fp16 [b,t,h*64+d]
    const int b = bh >> 4, h = bh & 15;
    #pragma unroll
    for (int r = 0; r < 2; r++) {
        float inv = 1.0f / l_r[r];
        int t = qi * 128 + w * 16 + g + r * 8;
        size_t rowo = ((size_t)(b * T_ + t)) * DM_ + h * 64;
        #pragma unroll
        for (int nt = 0; nt < 8; nt++) {
            int d = nt * 8 + 2 * tq;
            *(uint32_t*)(Ah + rowo + d) =
                pack_half2(oacc[nt][r*2] * inv, oacc[nt][r*2+1] * inv);
        }
    }
}

// ---------------------------------------------------------------------------
extern "C" void kernel_launch(void* const* d_in, const int* in_sizes, int n_in,
                              void* d_out, int out_size)
{
    const float* x   = (const float*)d_in[0];
    const float* Wq  = (const float*)d_in[2];
    const float* Wqb = (const float*)d_in[3];
    const float* Wk  = (const float*)d_in[4];
    const float* Wkb = (const float*)d_in[5];
    const float* Wv  = (const float*)d_in[6];
    const float* Wvb = (const float*)d_in[7];
    const float* Wo  = (const float*)d_in[8];
    const float* Wob = (const float*)d_in[9];
    float* out = (float*)d_out;

    __half *xh, *wh, *qh, *kh, *vh, *ah;
    cudaGetSymbolAddress((void**)&xh, g_xh);
    cudaGetSymbolAddress((void**)&wh, g_wh);
    cudaGetSymbolAddress((void**)&qh, g_qh);
    cudaGetSymbolAddress((void**)&kh, g_kh);
    cudaGetSymbolAddress((void**)&vh, g_vh);
    cudaGetSymbolAddress((void**)&ah, g_ah);

    cudaFuncSetAttribute(gemm_tc_kernel, cudaFuncAttributeMaxDynamicSharedMemorySize, G_SMEM);
    cudaFuncSetAttribute(attn_tc_kernel, cudaFuncAttributeMaxDynamicSharedMemorySize, ATTN_SMEM);

    const int nx4 = M_ * DM_ / 4, nw4 = DM_ * DM_ / 4;
    tohalf_kernel<<<nx4 / 256, 256>>>(x, xh, nx4);
    tohalf_w_kernel<<<dim3(nw4 / 256, 4), 256>>>(Wq, Wk, Wv, Wo, wh, nw4);

    // Fused QKV: N = 3072 (Wq|Wk|Wv rows contiguous in g_wh)
    gemm_tc_kernel<<<dim3(3 * DM_ / 128, M_ / 128), 256, G_SMEM>>>(
        xh, wh, Wqb, Wkb, Wvb, qh, kh, vh, nullptr, 0);

    attn_tc_kernel<<<dim3(T_ / 128, B_ * H_), 256, ATTN_SMEM>>>(qh, kh, vh, ah);

    // O-projection: fp32 out
    gemm_tc_kernel<<<dim3(DM_ / 128, M_ / 128), 256, G_SMEM>>>(
        ah, wh + 3 * DM_ * DM_, Wob, nullptr, nullptr,
        nullptr, nullptr, nullptr, out, 1);
}

// round 12
// speedup vs baseline: 1.0007x; 1.0007x over previous
#include <cuda_runtime.h>
#include <cuda_fp16.h>
#include <cstdint>

#define B_  4
#define H_  16
#define T_  2048
#define DK_ 64
#define DM_ 1024
#define M_  (B_*T_)     // 8192

// softmax scale folded into Q: 1/sqrt(64) * log2(e)
#define QSCALE 0.1803368801111204f

// ---------------- scratch (device globals; no allocations allowed) ----------
__device__ __half g_xh[M_*DM_];
__device__ __half g_wh[4*DM_*DM_];   // Wq | Wk | Wv | Wo (contiguous)
__device__ __half g_qh[M_*DM_];      // [b,h,t,d]  (pre-scaled by QSCALE)
__device__ __half g_kh[M_*DM_];      // [b,h,t,d]
__device__ __half g_vh[M_*DM_];      // [b,h,d,t]  (transposed!)
__device__ __half g_ah[M_*DM_];      // [b,t, h*64+d]

// ---------------- portable PTX helpers (family-safe) -------------------------
__device__ __forceinline__ uint32_t smem_u32(const void* p) {
    uint32_t a;
    asm("{ .reg .u64 t; cvta.to.shared.u64 t, %1; cvt.u32.u64 %0, t; }" : "=r"(a) : "l"(p));
    return a;
}
__device__ __forceinline__ void cp_async16(uint32_t saddr, const void* gaddr) {
    asm volatile("cp.async.cg.shared.global [%0], [%1], 16;" :: "r"(saddr), "l"(gaddr));
}
#define CP_COMMIT() asm volatile("cp.async.commit_group;" ::: "memory")
#define CP_WAIT(n)  asm volatile("cp.async.wait_group %0;" :: "n"(n) : "memory")

__device__ __forceinline__ void ldsm_x4(uint32_t addr, uint32_t& r0, uint32_t& r1,
                                        uint32_t& r2, uint32_t& r3) {
    asm volatile("ldmatrix.sync.aligned.m8n8.x4.shared.b16 {%0,%1,%2,%3}, [%4];"
                 : "=r"(r0), "=r"(r1), "=r"(r2), "=r"(r3) : "r"(addr));
}
__device__ __forceinline__ void mma_f16(float* c, const uint32_t* a, const uint32_t* b) {
    asm volatile(
        "mma.sync.aligned.m16n8k16.row.col.f32.f16.f16.f32 "
        "{%0,%1,%2,%3}, {%4,%5,%6,%7}, {%8,%9}, {%0,%1,%2,%3};"
        : "+f"(c[0]), "+f"(c[1]), "+f"(c[2]), "+f"(c[3])
        : "r"(a[0]), "r"(a[1]), "r"(a[2]), "r"(a[3]), "r"(b[0]), "r"(b[1]));
}
__device__ __forceinline__ uint32_t pack_half2(float a, float b) {
    __half2 h = __floats2half2_rn(a, b);
    return *(uint32_t*)&h;
}
__device__ __forceinline__ float ex2(float x) {
    float r;
    asm("ex2.approx.f32 %0, %1;" : "=f"(r) : "f"(x));
    return r;
}

// ---------------- fp32 -> fp16 converts ---------------------------------------
__global__ __launch_bounds__(256) void tohalf_kernel(
    const float* __restrict__ x, __half* __restrict__ y, int n4)
{
    int i = blockIdx.x * blockDim.x + threadIdx.x;
    if (i >= n4) return;
    float4 v = ((const float4*)x)[i];
    uint2 o;
    o.x = pack_half2(v.x, v.y);
    o.y = pack_half2(v.z, v.w);
    ((uint2*)y)[i] = o;
}

// all 4 weight matrices in one launch (grid.y selects source)
__global__ __launch_bounds__(256) void tohalf_w_kernel(
    const float* __restrict__ s0, const float* __restrict__ s1,
    const float* __restrict__ s2, const float* __restrict__ s3,
    __half* __restrict__ y, int n4)
{
    int i = blockIdx.x * blockDim.x + threadIdx.x;
    if (i >= n4) return;
    const float* src = (blockIdx.y == 0) ? s0 : (blockIdx.y == 1) ? s1
                     : (blockIdx.y == 2) ? s2 : s3;
    float4 v = ((const float4*)src)[i];
    uint2 o;
    o.x = pack_half2(v.x, v.y);
    o.y = pack_half2(v.z, v.w);
    ((uint2*)(y + (size_t)blockIdx.y * DM_ * DM_))[i] = o;
}

// ---------------- mma.sync fp16 GEMM -----------------------------------------
// CTA 128(m) x 128(n), BK=32, 4-stage cp.async, 256 thr = 8 warps 4(m)x2(n),
// warp tile 32x64. mode 0: fused QKV epilogue (N=3072, n>>10 selects Q/K/V;
// Q pre-scaled by QSCALE); mode 1: fp32 row-major out (+bias).
#define GPH 40                              // smem pitch (fp16): 80B rows
#define GT_BYTES (128 * GPH * 2)            // 10240 B per 128x32 tile
#define G_STAGE (2 * GT_BYTES)              // 20480 B (A, B)
#define G_SMEM (4 * G_STAGE)                // 81920 B -> 2 CTAs/SM

__device__ __forceinline__ void gemm_issue_stage(uint32_t base,
    const __half* __restrict__ Ah, const __half* __restrict__ Wh,
    int m0, int n0, int k0, int tid)
{
    // each tile: 128 rows x 64B (4 x 16B chunks) = 512 chunks / 256 thr = 2 iters
    #pragma unroll
    for (int it = 0; it < 2; it++) {
        int idx = it * 256 + tid;
        int r = idx >> 2, c = idx & 3;
        const uint32_t so = r * (GPH * 2) + c * 16;
        cp_async16(base + so,            Ah + (size_t)(m0 + r) * 1024 + k0 + c * 8);
        cp_async16(base + GT_BYTES + so, Wh + (size_t)(n0 + r) * 1024 + k0 + c * 8);
    }
}

__global__ __launch_bounds__(256, 2) void gemm_tc_kernel(
    const __half* __restrict__ Ah, const __half* __restrict__ Wh,
    const float* __restrict__ bias0, const float* __restrict__ bias1,
    const float* __restrict__ bias2,
    __half* __restrict__ Qh, __half* __restrict__ Kh, __half* __restrict__ Vh,
    float* __restrict__ Cf, int mode)
{
    extern __shared__ char smem[];
    const uint32_t sb = smem_u32(smem);
    const int tid = threadIdx.x;
    const int wid = tid >> 5, lane = tid & 31;
    const int m0 = blockIdx.y * 128, n0 = blockIdx.x * 128;
    const int wm = (wid & 3) * 32;        // warp m-offset
    const int wn = (wid >> 2) * 64;       // warp n-offset
    const int rl = lane & 7, q = lane >> 3;

    float acc[2][8][4];
    #pragma unroll
    for (int mt = 0; mt < 2; mt++)
        #pragma unroll
        for (int nt = 0; nt < 8; nt++)
            #pragma unroll
            for (int e = 0; e < 4; e++) acc[mt][nt][e] = 0.f;

    // prologue: stages 0..2 in flight
    #pragma unroll
    for (int p = 0; p < 3; p++) {
        gemm_issue_stage(sb + p * G_STAGE, Ah, Wh, m0, n0, p * 32, tid);
        CP_COMMIT();
    }

    const uint32_t a_row = rl + (q & 1) * 8;
    const uint32_t a_cofs = (q >> 1) * 8;
    const uint32_t b_row = rl + (q >> 1) * 8;
    const uint32_t b_cofs = (q & 1) * 8;

    for (int s = 0; s < 32; s++) {
        if (s <= 29)      CP_WAIT(2);
        else if (s == 30) CP_WAIT(1);
        else              CP_WAIT(0);
        __syncthreads();

        const uint32_t st = sb + (s & 3) * G_STAGE;

        #pragma unroll
        for (int kk = 0; kk < 2; kk++) {
            uint32_t af[2][4];
            #pragma unroll
            for (int mt = 0; mt < 2; mt++) {
                uint32_t ro = (wm + mt * 16 + a_row) * (GPH * 2) + (kk * 16 + a_cofs) * 2;
                ldsm_x4(st + ro, af[mt][0], af[mt][1], af[mt][2], af[mt][3]);
            }
            uint32_t bf[8][2];
            #pragma unroll
            for (int np = 0; np < 4; np++) {
                uint32_t ro = (wn + np * 16 + b_row) * (GPH * 2) + (kk * 16 + b_cofs) * 2;
                ldsm_x4(st + GT_BYTES + ro,
                        bf[np*2][0], bf[np*2][1], bf[np*2+1][0], bf[np*2+1][1]);
            }
            #pragma unroll
            for (int mt = 0; mt < 2; mt++)
                #pragma unroll
                for (int nt = 0; nt < 8; nt++)
                    mma_f16(acc[mt][nt], af[mt], bf[nt]);
        }

        if (s + 3 < 32) {
            gemm_issue_stage(sb + ((s + 3) & 3) * G_STAGE, Ah, Wh,
                             m0, n0, (s + 3) * 32, tid);
            CP_COMMIT();
        }
    }

    // ---- epilogue
    const int g = lane >> 2, tq = lane & 3;
    const int which = (n0 >> 10);   // CTA-uniform (tile never crosses 1024)
    const float* bsel = (which == 0) ? bias0 : (which == 1) ? bias1 : bias2;

    #pragma unroll
    for (int mt = 0; mt < 2; mt++) {
        #pragma unroll
        for (int half = 0; half < 2; half++) {
            int m = m0 + wm + mt * 16 + g + half * 8;
            int b = m >> 11, t = m & 2047;
            #pragma unroll
            for (int nt = 0; nt < 8; nt++) {
                int n = n0 + wn + nt * 8 + 2 * tq;
                if (mode == 1) {
                    float2 v;
                    v.x = acc[mt][nt][half * 2 + 0] + __ldg(bias0 + n);
                    v.y = acc[mt][nt][half * 2 + 1] + __ldg(bias0 + n + 1);
                    *(float2*)(Cf + (size_t)m * 1024 + n) = v;
                } else {
                    int nn = n & 1023;
                    float vx = acc[mt][nt][half * 2 + 0] + __ldg(bsel + nn);
                    float vy = acc[mt][nt][half * 2 + 1] + __ldg(bsel + nn + 1);
                    int h = nn >> 6, d = nn & 63;
                    if (which == 2) {
                        // V transposed: [b,h,d,t]
                        size_t off = (((size_t)(b * 16 + h)) * 64 + d) * 2048 + t;
                        Vh[off]        = __float2half_rn(vx);
                        Vh[off + 2048] = __float2half_rn(vy);
                    } else if (which == 0) {
                        // Q: fold softmax scale * log2(e) here
                        size_t off = (((size_t)(b * 16 + h)) * 2048 + t) * 64 + d;
                        *(uint32_t*)(Qh + off) = pack_half2(vx * QSCALE, vy * QSCALE);
                    } else {
                        size_t off = (((size_t)(b * 16 + h)) * 2048 + t) * 64 + d;
                        *(uint32_t*)(Kh + off) = pack_half2(vx, vy);
                    }
                }
            }
        }
    }
}

// ---------------- tensor-core flash attention (fp16, causal) -----------------
// grid (T/64, B*H), 128 thr = 4 warps; warp w owns Q rows w*16..w*16+15.
// Q pre-scaled; softmax in base-2 (ex2), mask applied only on diagonal tile.
#define AP 72                              // smem pitch in fp16 (144B rows)
#define ATILE (64 * AP * 2)                // 9216 B per 64x64 tile
#define AST_OFF ATILE                      // stages after Q tile
#define ASTAGE (2 * ATILE)                 // K, V
#define ATTN_SMEM (ATILE + 2 * ASTAGE)     // 46080 B

__device__ __forceinline__ void attn_load_tile(uint32_t sbase,
    const __half* __restrict__ gsrc, int rowstride, int tid)
{
    #pragma unroll
    for (int it = 0; it < 4; it++) {
        int idx = it * 128 + tid;          // 0..511
        int r = idx >> 3, c = idx & 7;
        cp_async16(sbase + r * (AP * 2) + c * 16,
                   gsrc + (size_t)r * rowstride + c * 8);
    }
}

__global__ __launch_bounds__(128, 3) void attn_tc_kernel(
    const __half* __restrict__ Qh, const __half* __restrict__ Kh,
    const __half* __restrict__ VTh, __half* __restrict__ Ah)
{
    extern __shared__ char smem[];
    const uint32_t sb = smem_u32(smem);
    const int tid = threadIdx.x;
    const int w = tid >> 5, lane = tid & 31;
    const int qi = blockIdx.x, bh = blockIdx.y;
    const size_t baseTD = (size_t)bh * T_ * 64;
    const int rl = lane & 7, q = lane >> 3;
    const int g = lane >> 2, tq = lane & 3;

    attn_load_tile(sb, Qh + baseTD + (size_t)qi * 64 * 64, 64, tid);
    CP_COMMIT();
    {
        uint32_t st0 = sb + AST_OFF;
        attn_load_tile(st0,         Kh + baseTD, 64, tid);
        attn_load_tile(st0 + ATILE, VTh + baseTD, 2048, tid);
        CP_COMMIT();
    }

    CP_WAIT(1);
    __syncthreads();

    const uint32_t a_row = rl + (q & 1) * 8, a_cofs = (q >> 1) * 8;
    const uint32_t b_row = rl + (q >> 1) * 8, b_cofs = (q & 1) * 8;
    uint32_t qf[4][4];
    #pragma unroll
    for (int kk = 0; kk < 4; kk++) {
        uint32_t ro = (w * 16 + a_row) * (AP * 2) + (kk * 16 + a_cofs) * 2;
        ldsm_x4(sb + ro, qf[kk][0], qf[kk][1], qf[kk][2], qf[kk][3]);
    }

    float oacc[8][4];
    #pragma unroll
    for (int nt = 0; nt < 8; nt++)
        #pragma unroll
        for (int e = 0; e < 4; e++) oacc[nt][e] = 0.f;
    float m_r[2] = {-1e30f, -1e30f}, l_r[2] = {0.f, 0.f};

    for (int kt = 0; kt <= qi; kt++) {
        const uint32_t st = sb + AST_OFF + (kt & 1) * ASTAGE;
        if (kt < qi) {
            uint32_t ns = sb + AST_OFF + ((kt + 1) & 1) * ASTAGE;
            attn_load_tile(ns,         Kh + baseTD + (size_t)(kt + 1) * 64 * 64, 64, tid);
            attn_load_tile(ns + ATILE, VTh + baseTD + (size_t)(kt + 1) * 64, 2048, tid);
            CP_COMMIT();
            CP_WAIT(1);
        } else {
            CP_WAIT(0);
        }
        __syncthreads();

        // ---- S = Q K^T  (already includes softmax scale * log2e via Q)
        float sacc[8][4];
        #pragma unroll
        for (int nt = 0; nt < 8; nt++)
            #pragma unroll
            for (int e = 0; e < 4; e++) sacc[nt][e] = 0.f;

        #pragma unroll
        for (int kk = 0; kk < 4; kk++) {
            uint32_t kf[8][2];
            #pragma unroll
            for (int np = 0; np < 4; np++) {
                uint32_t ro = (np * 16 + b_row) * (AP * 2) + (kk * 16 + b_cofs) * 2;
                ldsm_x4(st + ro,
                        kf[np*2][0], kf[np*2][1], kf[np*2+1][0], kf[np*2+1][1]);
            }
            #pragma unroll
            for (int nt = 0; nt < 8; nt++)
                mma_f16(sacc[nt], qf[kk], kf[nt]);
        }

        // ---- causal mask: only the diagonal tile needs it (CTA-uniform branch)
        if (kt == qi) {
            #pragma unroll
            for (int nt = 0; nt < 8; nt++) {
                #pragma unroll
                for (int e = 0; e < 4; e++) {
                    int row = w * 16 + g + (e >> 1) * 8;
                    int col = nt * 8 + 2 * tq + (e & 1);
                    if (col > row) sacc[nt][e] = -1e30f;
                }
            }
        }

        // ---- online softmax, base-2 (per thread: rows g, g+8)
        #pragma unroll
        for (int r = 0; r < 2; r++) {
            float mloc = -1e30f;
            #pragma unroll
            for (int nt = 0; nt < 8; nt++)
                mloc = fmaxf(mloc, fmaxf(sacc[nt][r*2], sacc[nt][r*2+1]));
            mloc = fmaxf(mloc, __shfl_xor_sync(0xffffffffu, mloc, 1));
            mloc = fmaxf(mloc, __shfl_xor_sync(0xffffffffu, mloc, 2));
            float mnew = fmaxf(m_r[r], mloc);
            float rs = 0.f;
            #pragma unroll
            for (int nt = 0; nt < 8; nt++) {
                float p0 = ex2(sacc[nt][r*2]   - mnew);
                float p1 = ex2(sacc[nt][r*2+1] - mnew);
                sacc[nt][r*2] = p0; sacc[nt][r*2+1] = p1;
                rs += p0 + p1;
            }
            rs += __shfl_xor_sync(0xffffffffu, rs, 1);
            rs += __shfl_xor_sync(0xffffffffu, rs, 2);
            float corr = ex2(m_r[r] - mnew);
            l_r[r] = l_r[r] * corr + rs;
            m_r[r] = mnew;
            #pragma unroll
            for (int nt = 0; nt < 8; nt++) {
                oacc[nt][r*2]   *= corr;
                oacc[nt][r*2+1] *= corr;
            }
        }

        // ---- O += P V
        #pragma unroll
        for (int j = 0; j < 4; j++) {
            uint32_t pf[4];
            pf[0] = pack_half2(sacc[2*j][0],   sacc[2*j][1]);
            pf[1] = pack_half2(sacc[2*j][2],   sacc[2*j][3]);
            pf[2] = pack_half2(sacc[2*j+1][0], sacc[2*j+1][1]);
            pf[3] = pack_half2(sacc[2*j+1][2], sacc[2*j+1][3]);

            uint32_t vf[8][2];
            #pragma unroll
            for (int np = 0; np < 4; np++) {
                uint32_t ro = (np * 16 + b_row) * (AP * 2) + (j * 16 + b_cofs) * 2;
                ldsm_x4(st + ATILE + ro,
                        vf[np*2][0], vf[np*2][1], vf[np*2+1][0], vf[np*2+1][1]);
            }
            #pragma unroll
            for (int nt = 0; nt < 8; nt++)
                mma_f16(oacc[nt], pf, vf[nt]);
        }
        __syncthreads();
    }

    // ---- epilogue: normalize, write fp16 [b,t,h*64+d]
    const int b = bh >> 4, h = bh & 15;
    #pragma unroll
    for (int r = 0; r < 2; r++) {
        float inv = 1.0f / l_r[r];
        int t = qi * 64 + w * 16 + g + r * 8;
        size_t rowo = ((size_t)(b * T_ + t)) * DM_ + h * 64;
        #pragma unroll
        for (int nt = 0; nt < 8; nt++) {
            int d = nt * 8 + 2 * tq;
            *(uint32_t*)(Ah + rowo + d) =
                pack_half2(oacc[nt][r*2] * inv, oacc[nt][r*2+1] * inv);
        }
    }
}

// ---------------------------------------------------------------------------
extern "C" void kernel_launch(void* const* d_in, const int* in_sizes, int n_in,
                              void* d_out, int out_size)
{
    const float* x   = (const float*)d_in[0];
    const float* Wq  = (const float*)d_in[2];
    const float* Wqb = (const float*)d_in[3];
    const float* Wk  = (const float*)d_in[4];
    const float* Wkb = (const float*)d_in[5];
    const float* Wv  = (const float*)d_in[6];
    const float* Wvb = (const float*)d_in[7];
    const float* Wo  = (const float*)d_in[8];
    const float* Wob = (const float*)d_in[9];
    float* out = (float*)d_out;

    __half *xh, *wh, *qh, *kh, *vh, *ah;
    cudaGetSymbolAddress((void**)&xh, g_xh);
    cudaGetSymbolAddress((void**)&wh, g_wh);
    cudaGetSymbolAddress((void**)&qh, g_qh);
    cudaGetSymbolAddress((void**)&kh, g_kh);
    cudaGetSymbolAddress((void**)&vh, g_vh);
    cudaGetSymbolAddress((void**)&ah, g_ah);

    cudaFuncSetAttribute(gemm_tc_kernel, cudaFuncAttributeMaxDynamicSharedMemorySize, G_SMEM);
    cudaFuncSetAttribute(attn_tc_kernel, cudaFuncAttributeMaxDynamicSharedMemorySize, ATTN_SMEM);

    const int nx4 = M_ * DM_ / 4, nw4 = DM_ * DM_ / 4;
    tohalf_kernel<<<nx4 / 256, 256>>>(x, xh, nx4);
    tohalf_w_kernel<<<dim3(nw4 / 256, 4), 256>>>(Wq, Wk, Wv, Wo, wh, nw4);

    // Fused QKV: N = 3072 (Wq|Wk|Wv rows contiguous in g_wh)
    gemm_tc_kernel<<<dim3(3 * DM_ / 128, M_ / 128), 256, G_SMEM>>>(
        xh, wh, Wqb, Wkb, Wvb, qh, kh, vh, nullptr, 0);

    attn_tc_kernel<<<dim3(T_ / 64, B_ * H_), 128, ATTN_SMEM>>>(qh, kh, vh, ah);

    // O-projection: fp32 out
    gemm_tc_kernel<<<dim3(DM_ / 128, M_ / 128), 256, G_SMEM>>>(
        ah, wh + 3 * DM_ * DM_, Wob, nullptr, nullptr,
        nullptr, nullptr, nullptr, out, 1);
}

// round 13
// speedup vs baseline: 1.4623x; 1.4612x over previous
#include <cuda_runtime.h>
#include <cuda_fp16.h>
#include <cstdint>

#define B_  4
#define H_  16
#define T_  2048
#define DK_ 64
#define DM_ 1024
#define M_  (B_*T_)     // 8192

// ---------------- scratch (device globals; no allocations allowed) ----------
__device__ __half g_xh[M_*DM_];
__device__ __half g_wh[4*DM_*DM_];   // Wq | Wk | Wv | Wo (contiguous)
__device__ __half g_qh[M_*DM_];      // [b,h,t,d]
__device__ __half g_kh[M_*DM_];      // [b,h,t,d]
__device__ __half g_vh[M_*DM_];      // [b,h,d,t]  (transposed!)
__device__ __half g_ah[M_*DM_];      // [b,t, h*64+d]

// ---------------- portable PTX helpers (family-safe) -------------------------
__device__ __forceinline__ uint32_t smem_u32(const void* p) {
    uint32_t a;
    asm("{ .reg .u64 t; cvta.to.shared.u64 t, %1; cvt.u32.u64 %0, t; }" : "=r"(a) : "l"(p));
    return a;
}
__device__ __forceinline__ void cp_async16(uint32_t saddr, const void* gaddr) {
    asm volatile("cp.async.cg.shared.global [%0], [%1], 16;" :: "r"(saddr), "l"(gaddr));
}
#define CP_COMMIT() asm volatile("cp.async.commit_group;" ::: "memory")
#define CP_WAIT(n)  asm volatile("cp.async.wait_group %0;" :: "n"(n) : "memory")

__device__ __forceinline__ void ldsm_x4(uint32_t addr, uint32_t& r0, uint32_t& r1,
                                        uint32_t& r2, uint32_t& r3) {
    asm volatile("ldmatrix.sync.aligned.m8n8.x4.shared.b16 {%0,%1,%2,%3}, [%4];"
                 : "=r"(r0), "=r"(r1), "=r"(r2), "=r"(r3) : "r"(addr));
}
__device__ __forceinline__ void mma_f16(float* c, const uint32_t* a, const uint32_t* b) {
    asm volatile(
        "mma.sync.aligned.m16n8k16.row.col.f32.f16.f16.f32 "
        "{%0,%1,%2,%3}, {%4,%5,%6,%7}, {%8,%9}, {%0,%1,%2,%3};"
        : "+f"(c[0]), "+f"(c[1]), "+f"(c[2]), "+f"(c[3])
        : "r"(a[0]), "r"(a[1]), "r"(a[2]), "r"(a[3]), "r"(b[0]), "r"(b[1]));
}
__device__ __forceinline__ uint32_t pack_half2(float a, float b) {
    __half2 h = __floats2half2_rn(a, b);
    return *(uint32_t*)&h;
}

// ---------------- fp32 -> fp16 convert ---------------------------------------
__global__ __launch_bounds__(256) void tohalf_kernel(
    const float* __restrict__ x, __half* __restrict__ y, int n4)
{
    int i = blockIdx.x * blockDim.x + threadIdx.x;
    if (i >= n4) return;
    float4 v = ((const float4*)x)[i];
    uint2 o;
    o.x = pack_half2(v.x, v.y);
    o.y = pack_half2(v.z, v.w);
    ((uint2*)y)[i] = o;
}

// ---------------- mma.sync fp16 GEMM -----------------------------------------
// CTA 128(m) x 128(n), BK=32, 4-stage cp.async, 256 thr = 8 warps 4(m)x2(n),
// warp tile 32x64. mode 0: fused QKV epilogue (N=3072, n>>10 selects Q/K/V);
// mode 1: fp32 row-major out (+bias).
#define GPH 40                              // smem pitch (fp16): 80B rows
#define GT_BYTES (128 * GPH * 2)            // 10240 B per 128x32 tile
#define G_STAGE (2 * GT_BYTES)              // 20480 B (A, B)
#define G_SMEM (4 * G_STAGE)                // 81920 B -> 2 CTAs/SM

__device__ __forceinline__ void gemm_issue_stage(uint32_t base,
    const __half* __restrict__ Ah, const __half* __restrict__ Wh,
    int m0, int n0, int k0, int tid)
{
    // each tile: 128 rows x 64B (4 x 16B chunks) = 512 chunks / 256 thr = 2 iters
    #pragma unroll
    for (int it = 0; it < 2; it++) {
        int idx = it * 256 + tid;
        int r = idx >> 2, c = idx & 3;
        const uint32_t so = r * (GPH * 2) + c * 16;
        cp_async16(base + so,            Ah + (size_t)(m0 + r) * 1024 + k0 + c * 8);
        cp_async16(base + GT_BYTES + so, Wh + (size_t)(n0 + r) * 1024 + k0 + c * 8);
    }
}

__global__ __launch_bounds__(256, 2) void gemm_tc_kernel(
    const __half* __restrict__ Ah, const __half* __restrict__ Wh,
    const float* __restrict__ bias0, const float* __restrict__ bias1,
    const float* __restrict__ bias2,
    __half* __restrict__ Qh, __half* __restrict__ Kh, __half* __restrict__ Vh,
    float* __restrict__ Cf, int mode)
{
    extern __shared__ char smem[];
    const uint32_t sb = smem_u32(smem);
    const int tid = threadIdx.x;
    const int wid = tid >> 5, lane = tid & 31;
    const int m0 = blockIdx.y * 128, n0 = blockIdx.x * 128;
    const int wm = (wid & 3) * 32;        // warp m-offset
    const int wn = (wid >> 2) * 64;       // warp n-offset
    const int rl = lane & 7, q = lane >> 3;

    float acc[2][8][4];
    #pragma unroll
    for (int mt = 0; mt < 2; mt++)
        #pragma unroll
        for (int nt = 0; nt < 8; nt++)
            #pragma unroll
            for (int e = 0; e < 4; e++) acc[mt][nt][e] = 0.f;

    // prologue: stages 0..2 in flight
    #pragma unroll
    for (int p = 0; p < 3; p++) {
        gemm_issue_stage(sb + p * G_STAGE, Ah, Wh, m0, n0, p * 32, tid);
        CP_COMMIT();
    }

    const uint32_t a_row = rl + (q & 1) * 8;
    const uint32_t a_cofs = (q >> 1) * 8;
    const uint32_t b_row = rl + (q >> 1) * 8;
    const uint32_t b_cofs = (q & 1) * 8;

    for (int s = 0; s < 32; s++) {
        if (s <= 29)      CP_WAIT(2);
        else if (s == 30) CP_WAIT(1);
        else              CP_WAIT(0);
        __syncthreads();

        const uint32_t st = sb + (s & 3) * G_STAGE;

        #pragma unroll
        for (int kk = 0; kk < 2; kk++) {
            uint32_t af[2][4];
            #pragma unroll
            for (int mt = 0; mt < 2; mt++) {
                uint32_t ro = (wm + mt * 16 + a_row) * (GPH * 2) + (kk * 16 + a_cofs) * 2;
                ldsm_x4(st + ro, af[mt][0], af[mt][1], af[mt][2], af[mt][3]);
            }
            uint32_t bf[8][2];
            #pragma unroll
            for (int np = 0; np < 4; np++) {
                uint32_t ro = (wn + np * 16 + b_row) * (GPH * 2) + (kk * 16 + b_cofs) * 2;
                ldsm_x4(st + GT_BYTES + ro,
                        bf[np*2][0], bf[np*2][1], bf[np*2+1][0], bf[np*2+1][1]);
            }
            #pragma unroll
            for (int mt = 0; mt < 2; mt++)
                #pragma unroll
                for (int nt = 0; nt < 8; nt++)
                    mma_f16(acc[mt][nt], af[mt], bf[nt]);
        }

        if (s + 3 < 32) {
            gemm_issue_stage(sb + ((s + 3) & 3) * G_STAGE, Ah, Wh,
                             m0, n0, (s + 3) * 32, tid);
            CP_COMMIT();
        }
    }

    // ---- epilogue
    const int g = lane >> 2, tq = lane & 3;
    const int which = (n0 >> 10);   // CTA-uniform (tile never crosses 1024)
    const float* bsel = (which == 0) ? bias0 : (which == 1) ? bias1 : bias2;

    #pragma unroll
    for (int mt = 0; mt < 2; mt++) {
        #pragma unroll
        for (int half = 0; half < 2; half++) {
            int m = m0 + wm + mt * 16 + g + half * 8;
            int b = m >> 11, t = m & 2047;
            #pragma unroll
            for (int nt = 0; nt < 8; nt++) {
                int n = n0 + wn + nt * 8 + 2 * tq;
                if (mode == 1) {
                    float2 v;
                    v.x = acc[mt][nt][half * 2 + 0] + __ldg(bias0 + n);
                    v.y = acc[mt][nt][half * 2 + 1] + __ldg(bias0 + n + 1);
                    *(float2*)(Cf + (size_t)m * 1024 + n) = v;
                } else {
                    int nn = n & 1023;
                    float vx = acc[mt][nt][half * 2 + 0] + __ldg(bsel + nn);
                    float vy = acc[mt][nt][half * 2 + 1] + __ldg(bsel + nn + 1);
                    int h = nn >> 6, d = nn & 63;
                    if (which == 2) {
                        // V transposed: [b,h,d,t]
                        size_t off = (((size_t)(b * 16 + h)) * 64 + d) * 2048 + t;
                        Vh[off]        = __float2half_rn(vx);
                        Vh[off + 2048] = __float2half_rn(vy);
                    } else {
                        size_t off = (((size_t)(b * 16 + h)) * 2048 + t) * 64 + d;
                        uint32_t pv = pack_half2(vx, vy);
                        if (which == 0) *(uint32_t*)(Qh + off) = pv;
                        else            *(uint32_t*)(Kh + off) = pv;
                    }
                }
            }
        }
    }
}

// ---------------- tensor-core flash attention (fp16, causal) -----------------
// grid (T/64, B*H), 128 thr = 4 warps; warp w owns Q rows w*16..w*16+15.
#define AP 72                              // smem pitch in fp16 (144B rows)
#define ATILE (64 * AP * 2)                // 9216 B per 64x64 tile
#define AST_OFF ATILE                      // stages after Q tile
#define ASTAGE (2 * ATILE)                 // K, V
#define ATTN_SMEM (ATILE + 2 * ASTAGE)     // 46080 B

__device__ __forceinline__ void attn_load_tile(uint32_t sbase,
    const __half* __restrict__ gsrc, int rowstride, int tid)
{
    #pragma unroll
    for (int it = 0; it < 4; it++) {
        int idx = it * 128 + tid;          // 0..511
        int r = idx >> 3, c = idx & 7;
        cp_async16(sbase + r * (AP * 2) + c * 16,
                   gsrc + (size_t)r * rowstride + c * 8);
    }
}

__global__ __launch_bounds__(128, 3) void attn_tc_kernel(
    const __half* __restrict__ Qh, const __half* __restrict__ Kh,
    const __half* __restrict__ VTh, __half* __restrict__ Ah)
{
    extern __shared__ char smem[];
    const uint32_t sb = smem_u32(smem);
    const int tid = threadIdx.x;
    const int w = tid >> 5, lane = tid & 31;
    const int qi = blockIdx.x, bh = blockIdx.y;
    const size_t baseTD = (size_t)bh * T_ * 64;
    const int rl = lane & 7, q = lane >> 3;
    const int g = lane >> 2, tq = lane & 3;

    attn_load_tile(sb, Qh + baseTD + (size_t)qi * 64 * 64, 64, tid);
    CP_COMMIT();
    {
        uint32_t st0 = sb + AST_OFF;
        attn_load_tile(st0,         Kh + baseTD, 64, tid);
        attn_load_tile(st0 + ATILE, VTh + baseTD, 2048, tid);
        CP_COMMIT();
    }

    CP_WAIT(1);
    __syncthreads();

    const uint32_t a_row = rl + (q & 1) * 8, a_cofs = (q >> 1) * 8;
    const uint32_t b_row = rl + (q >> 1) * 8, b_cofs = (q & 1) * 8;
    uint32_t qf[4][4];
    #pragma unroll
    for (int kk = 0; kk < 4; kk++) {
        uint32_t ro = (w * 16 + a_row) * (AP * 2) + (kk * 16 + a_cofs) * 2;
        ldsm_x4(sb + ro, qf[kk][0], qf[kk][1], qf[kk][2], qf[kk][3]);
    }

    float oacc[8][4];
    #pragma unroll
    for (int nt = 0; nt < 8; nt++)
        #pragma unroll
        for (int e = 0; e < 4; e++) oacc[nt][e] = 0.f;
    float m_r[2] = {-1e30f, -1e30f}, l_r[2] = {0.f, 0.f};

    for (int kt = 0; kt <= qi; kt++) {
        const uint32_t st = sb + AST_OFF + (kt & 1) * ASTAGE;
        if (kt < qi) {
            uint32_t ns = sb + AST_OFF + ((kt + 1) & 1) * ASTAGE;
            attn_load_tile(ns,         Kh + baseTD + (size_t)(kt + 1) * 64 * 64, 64, tid);
            attn_load_tile(ns + ATILE, VTh + baseTD + (size_t)(kt + 1) * 64, 2048, tid);
            CP_COMMIT();
            CP_WAIT(1);
        } else {
            CP_WAIT(0);
        }
        __syncthreads();

        // ---- S = Q K^T
        float sacc[8][4];
        #pragma unroll
        for (int nt = 0; nt < 8; nt++)
            #pragma unroll
            for (int e = 0; e < 4; e++) sacc[nt][e] = 0.f;

        #pragma unroll
        for (int kk = 0; kk < 4; kk++) {
            uint32_t kf[8][2];
            #pragma unroll
            for (int np = 0; np < 4; np++) {
                uint32_t ro = (np * 16 + b_row) * (AP * 2) + (kk * 16 + b_cofs) * 2;
                ldsm_x4(st + ro,
                        kf[np*2][0], kf[np*2][1], kf[np*2+1][0], kf[np*2+1][1]);
            }
            #pragma unroll
            for (int nt = 0; nt < 8; nt++)
                mma_f16(sacc[nt], qf[kk], kf[nt]);
        }

        // ---- scale + causal mask
        const bool diag = (kt == qi);
        #pragma unroll
        for (int nt = 0; nt < 8; nt++) {
            #pragma unroll
            for (int e = 0; e < 4; e++) {
                float s = sacc[nt][e] * 0.125f;
                if (diag) {
                    int row = w * 16 + g + (e >> 1) * 8;
                    int col = nt * 8 + 2 * tq + (e & 1);
                    if (col > row) s = -1e30f;
                }
                sacc[nt][e] = s;
            }
        }

        // ---- online softmax (per thread: rows g, g+8)
        #pragma unroll
        for (int r = 0; r < 2; r++) {
            float mloc = -1e30f;
            #pragma unroll
            for (int nt = 0; nt < 8; nt++)
                mloc = fmaxf(mloc, fmaxf(sacc[nt][r*2], sacc[nt][r*2+1]));
            mloc = fmaxf(mloc, __shfl_xor_sync(0xffffffffu, mloc, 1));
            mloc = fmaxf(mloc, __shfl_xor_sync(0xffffffffu, mloc, 2));
            float mnew = fmaxf(m_r[r], mloc);
            float rs = 0.f;
            #pragma unroll
            for (int nt = 0; nt < 8; nt++) {
                float p0 = __expf(sacc[nt][r*2]   - mnew);
                float p1 = __expf(sacc[nt][r*2+1] - mnew);
                sacc[nt][r*2] = p0; sacc[nt][r*2+1] = p1;
                rs += p0 + p1;
            }
            rs += __shfl_xor_sync(0xffffffffu, rs, 1);
            rs += __shfl_xor_sync(0xffffffffu, rs, 2);
            float corr = __expf(m_r[r] - mnew);
            l_r[r] = l_r[r] * corr + rs;
            m_r[r] = mnew;
            #pragma unroll
            for (int nt = 0; nt < 8; nt++) {
                oacc[nt][r*2]   *= corr;
                oacc[nt][r*2+1] *= corr;
            }
        }

        // ---- O += P V
        #pragma unroll
        for (int j = 0; j < 4; j++) {
            uint32_t pf[4];
            pf[0] = pack_half2(sacc[2*j][0],   sacc[2*j][1]);
            pf[1] = pack_half2(sacc[2*j][2],   sacc[2*j][3]);
            pf[2] = pack_half2(sacc[2*j+1][0], sacc[2*j+1][1]);
            pf[3] = pack_half2(sacc[2*j+1][2], sacc[2*j+1][3]);

            uint32_t vf[8][2];
            #pragma unroll
            for (int np = 0; np < 4; np++) {
                uint32_t ro = (np * 16 + b_row) * (AP * 2) + (j * 16 + b_cofs) * 2;
                ldsm_x4(st + ATILE + ro,
                        vf[np*2][0], vf[np*2][1], vf[np*2+1][0], vf[np*2+1][1]);
            }
            #pragma unroll
            for (int nt = 0; nt < 8; nt++)
                mma_f16(oacc[nt], pf, vf[nt]);
        }
        __syncthreads();
    }

    // ---- epilogue: normalize, write fp16 [b,t,h*64+d]
    const int b = bh >> 4, h = bh & 15;
    #pragma unroll
    for (int r = 0; r < 2; r++) {
        float inv = 1.0f / l_r[r];
        int t = qi * 64 + w * 16 + g + r * 8;
        size_t rowo = ((size_t)(b * T_ + t)) * DM_ + h * 64;
        #pragma unroll
        for (int nt = 0; nt < 8; nt++) {
            int d = nt * 8 + 2 * tq;
            *(uint32_t*)(Ah + rowo + d) =
                pack_half2(oacc[nt][r*2] * inv, oacc[nt][r*2+1] * inv);
        }
    }
}

// ---------------------------------------------------------------------------
extern "C" void kernel_launch(void* const* d_in, const int* in_sizes, int n_in,
                              void* d_out, int out_size)
{
    const float* x   = (const float*)d_in[0];
    const float* Wq  = (const float*)d_in[2];
    const float* Wqb = (const float*)d_in[3];
    const float* Wk  = (const float*)d_in[4];
    const float* Wkb = (const float*)d_in[5];
    const float* Wv  = (const float*)d_in[6];
    const float* Wvb = (const float*)d_in[7];
    const float* Wo  = (const float*)d_in[8];
    const float* Wob = (const float*)d_in[9];
    float* out = (float*)d_out;

    __half *xh, *wh, *qh, *kh, *vh, *ah;
    cudaGetSymbolAddress((void**)&xh, g_xh);
    cudaGetSymbolAddress((void**)&wh, g_wh);
    cudaGetSymbolAddress((void**)&qh, g_qh);
    cudaGetSymbolAddress((void**)&kh, g_kh);
    cudaGetSymbolAddress((void**)&vh, g_vh);
    cudaGetSymbolAddress((void**)&ah, g_ah);

    cudaFuncSetAttribute(gemm_tc_kernel, cudaFuncAttributeMaxDynamicSharedMemorySize, G_SMEM);
    cudaFuncSetAttribute(attn_tc_kernel, cudaFuncAttributeMaxDynamicSharedMemorySize, ATTN_SMEM);

    const int nx4 = M_ * DM_ / 4, nw4 = DM_ * DM_ / 4;
    tohalf_kernel<<<nx4 / 256, 256>>>(x, xh, nx4);
    tohalf_kernel<<<nw4 / 256, 256>>>(Wq, wh + 0 * DM_ * DM_, nw4);
    tohalf_kernel<<<nw4 / 256, 256>>>(Wk, wh + 1 * DM_ * DM_, nw4);
    tohalf_kernel<<<nw4 / 256, 256>>>(Wv, wh + 2 * DM_ * DM_, nw4);
    tohalf_kernel<<<nw4 / 256, 256>>>(Wo, wh + 3 * DM_ * DM_, nw4);

    // Fused QKV: N = 3072 (Wq|Wk|Wv rows contiguous in g_wh)
    gemm_tc_kernel<<<dim3(3 * DM_ / 128, M_ / 128), 256, G_SMEM>>>(
        xh, wh, Wqb, Wkb, Wvb, qh, kh, vh, nullptr, 0);

    attn_tc_kernel<<<dim3(T_ / 64, B_ * H_), 128, ATTN_SMEM>>>(qh, kh, vh, ah);

    // O-projection: fp32 out
    gemm_tc_kernel<<<dim3(DM_ / 128, M_ / 128), 256, G_SMEM>>>(
        ah, wh + 3 * DM_ * DM_, Wob, nullptr, nullptr,
        nullptr, nullptr, nullptr, out, 1);
}

// round 14
// speedup vs baseline: 1.5071x; 1.0306x over previous
#include <cuda_runtime.h>
#include <cuda_fp16.h>
#include <cstdint>

#define B_  4
#define H_  16
#define T_  2048
#define DK_ 64
#define DM_ 1024
#define M_  (B_*T_)     // 8192

// softmax scale folded into Q: 1/sqrt(64) * log2(e)
#define QSCALE 0.1803368801111204f

// ---------------- scratch (device globals; no allocations allowed) ----------
__device__ __half g_xh[M_*DM_];
__device__ __half g_wh[4*DM_*DM_];   // Wq | Wk | Wv | Wo (contiguous)
__device__ __half g_qh[M_*DM_];      // [b,h,t,d]  (pre-scaled by QSCALE)
__device__ __half g_kh[M_*DM_];      // [b,h,t,d]
__device__ __half g_vh[M_*DM_];      // [b,h,d,t]  (transposed!)
__device__ __half g_ah[M_*DM_];      // [b,t, h*64+d]

// ---------------- portable PTX helpers (family-safe) -------------------------
__device__ __forceinline__ uint32_t smem_u32(const void* p) {
    uint32_t a;
    asm("{ .reg .u64 t; cvta.to.shared.u64 t, %1; cvt.u32.u64 %0, t; }" : "=r"(a) : "l"(p));
    return a;
}
__device__ __forceinline__ void cp_async16(uint32_t saddr, const void* gaddr) {
    asm volatile("cp.async.cg.shared.global [%0], [%1], 16;" :: "r"(saddr), "l"(gaddr));
}
#define CP_COMMIT() asm volatile("cp.async.commit_group;" ::: "memory")
#define CP_WAIT(n)  asm volatile("cp.async.wait_group %0;" :: "n"(n) : "memory")

__device__ __forceinline__ void ldsm_x4(uint32_t addr, uint32_t& r0, uint32_t& r1,
                                        uint32_t& r2, uint32_t& r3) {
    asm volatile("ldmatrix.sync.aligned.m8n8.x4.shared.b16 {%0,%1,%2,%3}, [%4];"
                 : "=r"(r0), "=r"(r1), "=r"(r2), "=r"(r3) : "r"(addr));
}
__device__ __forceinline__ void mma_f16(float* c, const uint32_t* a, const uint32_t* b) {
    asm volatile(
        "mma.sync.aligned.m16n8k16.row.col.f32.f16.f16.f32 "
        "{%0,%1,%2,%3}, {%4,%5,%6,%7}, {%8,%9}, {%0,%1,%2,%3};"
        : "+f"(c[0]), "+f"(c[1]), "+f"(c[2]), "+f"(c[3])
        : "r"(a[0]), "r"(a[1]), "r"(a[2]), "r"(a[3]), "r"(b[0]), "r"(b[1]));
}
__device__ __forceinline__ uint32_t pack_half2(float a, float b) {
    __half2 h = __floats2half2_rn(a, b);
    return *(uint32_t*)&h;
}
__device__ __forceinline__ float ex2(float x) {
    float r;
    asm("ex2.approx.f32 %0, %1;" : "=f"(r) : "f"(x));
    return r;
}

// ---------------- fp32 -> fp16 convert ---------------------------------------
__global__ __launch_bounds__(256) void tohalf_kernel(
    const float* __restrict__ x, __half* __restrict__ y, int n4)
{
    int i = blockIdx.x * blockDim.x + threadIdx.x;
    if (i >= n4) return;
    float4 v = ((const float4*)x)[i];
    uint2 o;
    o.x = pack_half2(v.x, v.y);
    o.y = pack_half2(v.z, v.w);
    ((uint2*)y)[i] = o;
}

// ---------------- mma.sync fp16 GEMM -----------------------------------------
// CTA 128(m) x 128(n), BK=32, 4-stage cp.async, 256 thr = 8 warps 4(m)x2(n),
// warp tile 32x64. mode 0: fused QKV epilogue (N=3072, n>>10 selects Q/K/V;
// Q pre-scaled by QSCALE); mode 1: fp32 row-major out (+bias).
#define GPH 40                              // smem pitch (fp16): 80B rows
#define GT_BYTES (128 * GPH * 2)            // 10240 B per 128x32 tile
#define G_STAGE (2 * GT_BYTES)              // 20480 B (A, B)
#define G_SMEM (4 * G_STAGE)                // 81920 B -> 2 CTAs/SM

__device__ __forceinline__ void gemm_issue_stage(uint32_t base,
    const __half* __restrict__ Ah, const __half* __restrict__ Wh,
    int m0, int n0, int k0, int tid)
{
    // each tile: 128 rows x 64B (4 x 16B chunks) = 512 chunks / 256 thr = 2 iters
    #pragma unroll
    for (int it = 0; it < 2; it++) {
        int idx = it * 256 + tid;
        int r = idx >> 2, c = idx & 3;
        const uint32_t so = r * (GPH * 2) + c * 16;
        cp_async16(base + so,            Ah + (size_t)(m0 + r) * 1024 + k0 + c * 8);
        cp_async16(base + GT_BYTES + so, Wh + (size_t)(n0 + r) * 1024 + k0 + c * 8);
    }
}

__global__ __launch_bounds__(256, 2) void gemm_tc_kernel(
    const __half* __restrict__ Ah, const __half* __restrict__ Wh,
    const float* __restrict__ bias0, const float* __restrict__ bias1,
    const float* __restrict__ bias2,
    __half* __restrict__ Qh, __half* __restrict__ Kh, __half* __restrict__ Vh,
    float* __restrict__ Cf, int mode)
{
    extern __shared__ char smem[];
    const uint32_t sb = smem_u32(smem);
    const int tid = threadIdx.x;
    const int wid = tid >> 5, lane = tid & 31;
    const int m0 = blockIdx.y * 128, n0 = blockIdx.x * 128;
    const int wm = (wid & 3) * 32;        // warp m-offset
    const int wn = (wid >> 2) * 64;       // warp n-offset
    const int rl = lane & 7, q = lane >> 3;

    float acc[2][8][4];
    #pragma unroll
    for (int mt = 0; mt < 2; mt++)
        #pragma unroll
        for (int nt = 0; nt < 8; nt++)
            #pragma unroll
            for (int e = 0; e < 4; e++) acc[mt][nt][e] = 0.f;

    // prologue: stages 0..2 in flight
    #pragma unroll
    for (int p = 0; p < 3; p++) {
        gemm_issue_stage(sb + p * G_STAGE, Ah, Wh, m0, n0, p * 32, tid);
        CP_COMMIT();
    }

    const uint32_t a_row = rl + (q & 1) * 8;
    const uint32_t a_cofs = (q >> 1) * 8;
    const uint32_t b_row = rl + (q >> 1) * 8;
    const uint32_t b_cofs = (q & 1) * 8;

    for (int s = 0; s < 32; s++) {
        if (s <= 29)      CP_WAIT(2);
        else if (s == 30) CP_WAIT(1);
        else              CP_WAIT(0);
        __syncthreads();

        const uint32_t st = sb + (s & 3) * G_STAGE;

        #pragma unroll
        for (int kk = 0; kk < 2; kk++) {
            uint32_t af[2][4];
            #pragma unroll
            for (int mt = 0; mt < 2; mt++) {
                uint32_t ro = (wm + mt * 16 + a_row) * (GPH * 2) + (kk * 16 + a_cofs) * 2;
                ldsm_x4(st + ro, af[mt][0], af[mt][1], af[mt][2], af[mt][3]);
            }
            uint32_t bf[8][2];
            #pragma unroll
            for (int np = 0; np < 4; np++) {
                uint32_t ro = (wn + np * 16 + b_row) * (GPH * 2) + (kk * 16 + b_cofs) * 2;
                ldsm_x4(st + GT_BYTES + ro,
                        bf[np*2][0], bf[np*2][1], bf[np*2+1][0], bf[np*2+1][1]);
            }
            #pragma unroll
            for (int mt = 0; mt < 2; mt++)
                #pragma unroll
                for (int nt = 0; nt < 8; nt++)
                    mma_f16(acc[mt][nt], af[mt], bf[nt]);
        }

        if (s + 3 < 32) {
            gemm_issue_stage(sb + ((s + 3) & 3) * G_STAGE, Ah, Wh,
                             m0, n0, (s + 3) * 32, tid);
            CP_COMMIT();
        }
    }

    // ---- epilogue
    const int g = lane >> 2, tq = lane & 3;
    const int which = (n0 >> 10);   // CTA-uniform (tile never crosses 1024)
    const float* bsel = (which == 0) ? bias0 : (which == 1) ? bias1 : bias2;

    #pragma unroll
    for (int mt = 0; mt < 2; mt++) {
        #pragma unroll
        for (int half = 0; half < 2; half++) {
            int m = m0 + wm + mt * 16 + g + half * 8;
            int b = m >> 11, t = m & 2047;
            #pragma unroll
            for (int nt = 0; nt < 8; nt++) {
                int n = n0 + wn + nt * 8 + 2 * tq;
                if (mode == 1) {
                    float2 v;
                    v.x = acc[mt][nt][half * 2 + 0] + __ldg(bias0 + n);
                    v.y = acc[mt][nt][half * 2 + 1] + __ldg(bias0 + n + 1);
                    *(float2*)(Cf + (size_t)m * 1024 + n) = v;
                } else {
                    int nn = n & 1023;
                    float vx = acc[mt][nt][half * 2 + 0] + __ldg(bsel + nn);
                    float vy = acc[mt][nt][half * 2 + 1] + __ldg(bsel + nn + 1);
                    int h = nn >> 6, d = nn & 63;
                    if (which == 2) {
                        // V transposed: [b,h,d,t]
                        size_t off = (((size_t)(b * 16 + h)) * 64 + d) * 2048 + t;
                        Vh[off]        = __float2half_rn(vx);
                        Vh[off + 2048] = __float2half_rn(vy);
                    } else if (which == 0) {
                        // Q: fold softmax scale * log2(e) here
                        size_t off = (((size_t)(b * 16 + h)) * 2048 + t) * 64 + d;
                        *(uint32_t*)(Qh + off) = pack_half2(vx * QSCALE, vy * QSCALE);
                    } else {
                        size_t off = (((size_t)(b * 16 + h)) * 2048 + t) * 64 + d;
                        *(uint32_t*)(Kh + off) = pack_half2(vx, vy);
                    }
                }
            }
        }
    }
}

// ---------------- tensor-core flash attention (fp16, causal) -----------------
// grid (T/64, B*H), 128 thr = 4 warps; warp w owns Q rows w*16..w*16+15.
// Q pre-scaled; softmax in base-2 (ex2), mask applied only on diagonal tile.
#define AP 72                              // smem pitch in fp16 (144B rows)
#define ATILE (64 * AP * 2)                // 9216 B per 64x64 tile
#define AST_OFF ATILE                      // stages after Q tile
#define ASTAGE (2 * ATILE)                 // K, V
#define ATTN_SMEM (ATILE + 2 * ASTAGE)     // 46080 B

__device__ __forceinline__ void attn_load_tile(uint32_t sbase,
    const __half* __restrict__ gsrc, int rowstride, int tid)
{
    #pragma unroll
    for (int it = 0; it < 4; it++) {
        int idx = it * 128 + tid;          // 0..511
        int r = idx >> 3, c = idx & 7;
        cp_async16(sbase + r * (AP * 2) + c * 16,
                   gsrc + (size_t)r * rowstride + c * 8);
    }
}

__global__ __launch_bounds__(128, 3) void attn_tc_kernel(
    const __half* __restrict__ Qh, const __half* __restrict__ Kh,
    const __half* __restrict__ VTh, __half* __restrict__ Ah)
{
    extern __shared__ char smem[];
    const uint32_t sb = smem_u32(smem);
    const int tid = threadIdx.x;
    const int w = tid >> 5, lane = tid & 31;
    const int qi = blockIdx.x, bh = blockIdx.y;
    const size_t baseTD = (size_t)bh * T_ * 64;
    const int rl = lane & 7, q = lane >> 3;
    const int g = lane >> 2, tq = lane & 3;

    attn_load_tile(sb, Qh + baseTD + (size_t)qi * 64 * 64, 64, tid);
    CP_COMMIT();
    {
        uint32_t st0 = sb + AST_OFF;
        attn_load_tile(st0,         Kh + baseTD, 64, tid);
        attn_load_tile(st0 + ATILE, VTh + baseTD, 2048, tid);
        CP_COMMIT();
    }

    CP_WAIT(1);
    __syncthreads();

    const uint32_t a_row = rl + (q & 1) * 8, a_cofs = (q >> 1) * 8;
    const uint32_t b_row = rl + (q >> 1) * 8, b_cofs = (q & 1) * 8;
    uint32_t qf[4][4];
    #pragma unroll
    for (int kk = 0; kk < 4; kk++) {
        uint32_t ro = (w * 16 + a_row) * (AP * 2) + (kk * 16 + a_cofs) * 2;
        ldsm_x4(sb + ro, qf[kk][0], qf[kk][1], qf[kk][2], qf[kk][3]);
    }

    float oacc[8][4];
    #pragma unroll
    for (int nt = 0; nt < 8; nt++)
        #pragma unroll
        for (int e = 0; e < 4; e++) oacc[nt][e] = 0.f;
    float m_r[2] = {-1e30f, -1e30f}, l_r[2] = {0.f, 0.f};

    for (int kt = 0; kt <= qi; kt++) {
        const uint32_t st = sb + AST_OFF + (kt & 1) * ASTAGE;
        if (kt < qi) {
            uint32_t ns = sb + AST_OFF + ((kt + 1) & 1) * ASTAGE;
            attn_load_tile(ns,         Kh + baseTD + (size_t)(kt + 1) * 64 * 64, 64, tid);
            attn_load_tile(ns + ATILE, VTh + baseTD + (size_t)(kt + 1) * 64, 2048, tid);
            CP_COMMIT();
            CP_WAIT(1);
        } else {
            CP_WAIT(0);
        }
        __syncthreads();

        // ---- S = Q K^T  (includes softmax scale * log2e via pre-scaled Q)
        float sacc[8][4];
        #pragma unroll
        for (int nt = 0; nt < 8; nt++)
            #pragma unroll
            for (int e = 0; e < 4; e++) sacc[nt][e] = 0.f;

        #pragma unroll
        for (int kk = 0; kk < 4; kk++) {
            uint32_t kf[8][2];
            #pragma unroll
            for (int np = 0; np < 4; np++) {
                uint32_t ro = (np * 16 + b_row) * (AP * 2) + (kk * 16 + b_cofs) * 2;
                ldsm_x4(st + ro,
                        kf[np*2][0], kf[np*2][1], kf[np*2+1][0], kf[np*2+1][1]);
            }
            #pragma unroll
            for (int nt = 0; nt < 8; nt++)
                mma_f16(sacc[nt], qf[kk], kf[nt]);
        }

        // ---- causal mask: only the diagonal tile (CTA-uniform branch)
        if (kt == qi) {
            #pragma unroll
            for (int nt = 0; nt < 8; nt++) {
                #pragma unroll
                for (int e = 0; e < 4; e++) {
                    int row = w * 16 + g + (e >> 1) * 8;
                    int col = nt * 8 + 2 * tq + (e & 1);
                    if (col > row) sacc[nt][e] = -1e30f;
                }
            }
        }

        // ---- online softmax, base-2 (per thread: rows g, g+8)
        #pragma unroll
        for (int r = 0; r < 2; r++) {
            float mloc = -1e30f;
            #pragma unroll
            for (int nt = 0; nt < 8; nt++)
                mloc = fmaxf(mloc, fmaxf(sacc[nt][r*2], sacc[nt][r*2+1]));
            mloc = fmaxf(mloc, __shfl_xor_sync(0xffffffffu, mloc, 1));
            mloc = fmaxf(mloc, __shfl_xor_sync(0xffffffffu, mloc, 2));
            float mnew = fmaxf(m_r[r], mloc);
            float rs = 0.f;
            #pragma unroll
            for (int nt = 0; nt < 8; nt++) {
                float p0 = ex2(sacc[nt][r*2]   - mnew);
                float p1 = ex2(sacc[nt][r*2+1] - mnew);
                sacc[nt][r*2] = p0; sacc[nt][r*2+1] = p1;
                rs += p0 + p1;
            }
            rs += __shfl_xor_sync(0xffffffffu, rs, 1);
            rs += __shfl_xor_sync(0xffffffffu, rs, 2);
            float corr = ex2(m_r[r] - mnew);
            l_r[r] = l_r[r] * corr + rs;
            m_r[r] = mnew;
            #pragma unroll
            for (int nt = 0; nt < 8; nt++) {
                oacc[nt][r*2]   *= corr;
                oacc[nt][r*2+1] *= corr;
            }
        }

        // ---- O += P V
        #pragma unroll
        for (int j = 0; j < 4; j++) {
            uint32_t pf[4];
            pf[0] = pack_half2(sacc[2*j][0],   sacc[2*j][1]);
            pf[1] = pack_half2(sacc[2*j][2],   sacc[2*j][3]);
            pf[2] = pack_half2(sacc[2*j+1][0], sacc[2*j+1][1]);
            pf[3] = pack_half2(sacc[2*j+1][2], sacc[2*j+1][3]);

            uint32_t vf[8][2];
            #pragma unroll
            for (int np = 0; np < 4; np++) {
                uint32_t ro = (np * 16 + b_row) * (AP * 2) + (j * 16 + b_cofs) * 2;
                ldsm_x4(st + ATILE + ro,
                        vf[np*2][0], vf[np*2][1], vf[np*2+1][0], vf[np*2+1][1]);
            }
            #pragma unroll
            for (int nt = 0; nt < 8; nt++)
                mma_f16(oacc[nt], pf, vf[nt]);
        }
        __syncthreads();
    }

    // ---- epilogue: normalize, write fp16 [b,t,h*64+d]
    const int b = bh >> 4, h = bh & 15;
    #pragma unroll
    for (int r = 0; r < 2; r++) {
        float inv = 1.0f / l_r[r];
        int t = qi * 64 + w * 16 + g + r * 8;
        size_t rowo = ((size_t)(b * T_ + t)) * DM_ + h * 64;
        #pragma unroll
        for (int nt = 0; nt < 8; nt++) {
            int d = nt * 8 + 2 * tq;
            *(uint32_t*)(Ah + rowo + d) =
                pack_half2(oacc[nt][r*2] * inv, oacc[nt][r*2+1] * inv);
        }
    }
}

// ---------------------------------------------------------------------------
extern "C" void kernel_launch(void* const* d_in, const int* in_sizes, int n_in,
                              void* d_out, int out_size)
{
    const float* x   = (const float*)d_in[0];
    const float* Wq  = (const float*)d_in[2];
    const float* Wqb = (const float*)d_in[3];
    const float* Wk  = (const float*)d_in[4];
    const float* Wkb = (const float*)d_in[5];
    const float* Wv  = (const float*)d_in[6];
    const float* Wvb = (const float*)d_in[7];
    const float* Wo  = (const float*)d_in[8];
    const float* Wob = (const float*)d_in[9];
    float* out = (float*)d_out;

    __half *xh, *wh, *qh, *kh, *vh, *ah;
    cudaGetSymbolAddress((void**)&xh, g_xh);
    cudaGetSymbolAddress((void**)&wh, g_wh);
    cudaGetSymbolAddress((void**)&qh, g_qh);
    cudaGetSymbolAddress((void**)&kh, g_kh);
    cudaGetSymbolAddress((void**)&vh, g_vh);
    cudaGetSymbolAddress((void**)&ah, g_ah);

    cudaFuncSetAttribute(gemm_tc_kernel, cudaFuncAttributeMaxDynamicSharedMemorySize, G_SMEM);
    cudaFuncSetAttribute(attn_tc_kernel, cudaFuncAttributeMaxDynamicSharedMemorySize, ATTN_SMEM);

    const int nx4 = M_ * DM_ / 4, nw4 = DM_ * DM_ / 4;
    tohalf_kernel<<<nx4 / 256, 256>>>(x, xh, nx4);
    tohalf_kernel<<<nw4 / 256, 256>>>(Wq, wh + 0 * DM_ * DM_, nw4);
    tohalf_kernel<<<nw4 / 256, 256>>>(Wk, wh + 1 * DM_ * DM_, nw4);
    tohalf_kernel<<<nw4 / 256, 256>>>(Wv, wh + 2 * DM_ * DM_, nw4);
    tohalf_kernel<<<nw4 / 256, 256>>>(Wo, wh + 3 * DM_ * DM_, nw4);

    // Fused QKV: N = 3072 (Wq|Wk|Wv rows contiguous in g_wh)
    gemm_tc_kernel<<<dim3(3 * DM_ / 128, M_ / 128), 256, G_SMEM>>>(
        xh, wh, Wqb, Wkb, Wvb, qh, kh, vh, nullptr, 0);

    attn_tc_kernel<<<dim3(T_ / 64, B_ * H_), 128, ATTN_SMEM>>>(qh, kh, vh, ah);

    // O-projection: fp32 out
    gemm_tc_kernel<<<dim3(DM_ / 128, M_ / 128), 256, G_SMEM>>>(
        ah, wh + 3 * DM_ * DM_, Wob, nullptr, nullptr,
        nullptr, nullptr, nullptr, out, 1);
}